// round 10
// baseline (speedup 1.0000x reference)
#include <cuda_runtime.h>

#define NN 100000
#define NE 1200000
#define NB1 98   // ceil(NN/1024) scan blocks

// Scratch (device globals — no allocation allowed).
__device__ int    g_is64;           // 1 if edge_index arrives as int64
__device__ int    g_deg[NN];        // in-degree
__device__ int    g_cur[NN];        // scan -> segment start; after fill -> segment end
__device__ int    g_bsum[128];      // scan block sums
__device__ int    g_esrc[NE];       // CSR: source node per edge slot (grouped by dst)
__device__ float4 g_h[NN * 16];     // relu(layer1)  [NN,64]
__device__ float4 g_hl[NN * 8];     // h @ W2_l      [NN,32]

// Edge fetch: harness may deliver edge_index as int32 (downcast) or raw int64
// (low word at even slot; ids < 100000 so high words are 0).
__device__ __forceinline__ int edge_src(const int* __restrict__ ei, int e) {
    return g_is64 ? __ldg(&ei[2 * e]) : __ldg(&ei[e]);
}
__device__ __forceinline__ int edge_dst(const int* __restrict__ ei, int e) {
    return g_is64 ? __ldg(&ei[2 * NE + 2 * e]) : __ldg(&ei[NE + e]);
}

// ---------------------------------------------------------------------------
// K0: zero degree histogram + dtype sniff (thread 0)
// ---------------------------------------------------------------------------
__global__ void k_zero(const int* __restrict__ ei) {
    int t = blockIdx.x * blockDim.x + threadIdx.x;
    if (t == 0) {
        int o = ei[1] | ei[3] | ei[5] | ei[7];
        g_is64 = (o == 0) ? 1 : 0;
    }
    if (t < NN) g_deg[t] = 0;
}

// ---------------------------------------------------------------------------
// K1: degree histogram (int atomics; index-guarded)
// ---------------------------------------------------------------------------
__global__ void k_deg(const int* __restrict__ ei) {
    int e = blockIdx.x * blockDim.x + threadIdx.x;
    if (e >= NE) return;
    unsigned dst = (unsigned)edge_dst(ei, e);
    if (dst < NN) atomicAdd(&g_deg[dst], 1);
}

// ---------------------------------------------------------------------------
// K2: per-block exclusive scan of g_deg (1024/block) — warp-shuffle version
// ---------------------------------------------------------------------------
__global__ void __launch_bounds__(256) k_scan1() {
    __shared__ int ws[8];
    int b = blockIdx.x, t = threadIdx.x;
    int base = b * 1024 + t * 4;
    int v0 = (base + 0 < NN) ? g_deg[base + 0] : 0;
    int v1 = (base + 1 < NN) ? g_deg[base + 1] : 0;
    int v2 = (base + 2 < NN) ? g_deg[base + 2] : 0;
    int v3 = (base + 3 < NN) ? g_deg[base + 3] : 0;
    int tsum = v0 + v1 + v2 + v3;

    int lane = t & 31, w = t >> 5;
    int v = tsum;
#pragma unroll
    for (int off = 1; off < 32; off <<= 1) {
        int y = __shfl_up_sync(0xffffffffu, v, off);
        if (lane >= off) v += y;
    }
    if (lane == 31) ws[w] = v;
    __syncthreads();
    if (t == 0) {
        int a = 0;
#pragma unroll
        for (int i = 0; i < 8; i++) { int x = ws[i]; ws[i] = a; a += x; }
        g_bsum[b] = a;                 // block total
    }
    __syncthreads();

    int p = (v - tsum) + ws[w];        // exclusive prefix within block
    if (base + 0 < NN) g_cur[base + 0] = p;
    p += v0;
    if (base + 1 < NN) g_cur[base + 1] = p;
    p += v1;
    if (base + 2 < NN) g_cur[base + 2] = p;
    p += v2;
    if (base + 3 < NN) g_cur[base + 3] = p;
}

// K2b: exclusive scan of the 98 block sums (parallel, 1 block)
__global__ void __launch_bounds__(128) k_scan2() {
    __shared__ int s[128];
    int t = threadIdx.x;
    int own = (t < NB1) ? g_bsum[t] : 0;
    s[t] = own;
    __syncthreads();
#pragma unroll
    for (int off = 1; off < 128; off <<= 1) {
        int x = (t >= off) ? s[t - off] : 0;
        __syncthreads();
        s[t] += x;
        __syncthreads();
    }
    if (t < NB1) g_bsum[t] = s[t] - own;   // exclusive
}

// K2c: add block offsets -> g_cur[i] = global segment start
__global__ void k_scan3() {
    int i = blockIdx.x * blockDim.x + threadIdx.x;
    if (i < NN) g_cur[i] += g_bsum[i >> 10];
}

// ---------------------------------------------------------------------------
// K3: fill CSR edge array. After this, g_cur[n] == segment END for node n.
// ---------------------------------------------------------------------------
__global__ void k_fill(const int* __restrict__ ei) {
    int e = blockIdx.x * blockDim.x + threadIdx.x;
    if (e >= NE) return;
    unsigned src = (unsigned)edge_src(ei, e);
    unsigned dst = (unsigned)edge_dst(ei, e);
    if (src >= NN || dst >= NN) return;
    int pos = atomicAdd(&g_cur[dst], 1);
    if ((unsigned)pos < NE) g_esrc[pos] = (int)src;
}

// ---------------------------------------------------------------------------
// K4: fused layer 1 + hl.
// Phase A (gather, 4x unrolled): 32 nodes x 16 chan-chunks; mean-agg x.
// Phase B (dense): h = relu(agg @ W1_l + x @ W1_r + b1) -> g_h and smem.
// Phase C (fused hl): hl = h @ W2_l, k-sum split across lane halves,
//   combined via shfl.down. Saves the separate k_hl kernel.
// Static smem exactly 48KB: sWl 16K + sWr 16K + sW2l 8K + sAgg 8K.
// NN == 3125*32 exactly: no tail guards needed.
// ---------------------------------------------------------------------------
__global__ void __launch_bounds__(512) k_layer1(const float4* __restrict__ x4,
                                                const float4* __restrict__ Wl,
                                                const float4* __restrict__ Wr,
                                                const float4* __restrict__ W2l,
                                                const float4* __restrict__ b1) {
    __shared__ float4 sWl[1024];
    __shared__ float4 sWr[1024];
    __shared__ float4 sW2l[512];
    __shared__ float4 sAgg[32 * 16];
    int tid = threadIdx.x;
    for (int i = tid; i < 1024; i += 512) { sWl[i] = Wl[i]; sWr[i] = Wr[i]; }
    sW2l[tid] = W2l[tid];

    int slot = tid >> 4;           // 0..31
    int c    = tid & 15;           // channel chunk / output j4
    int n    = blockIdx.x * 32 + slot;

    // --- Phase A: gather (4x unrolled, two accumulators) ---
    int end = g_cur[n];
    int d   = g_deg[n];
    int j   = end - d;
    float4 a0 = make_float4(0.f, 0.f, 0.f, 0.f);
    float4 a1 = make_float4(0.f, 0.f, 0.f, 0.f);
    for (; j + 4 <= end; j += 4) {
        int i0 = __ldg(&g_esrc[j + 0]);
        int i1 = __ldg(&g_esrc[j + 1]);
        int i2 = __ldg(&g_esrc[j + 2]);
        int i3 = __ldg(&g_esrc[j + 3]);
        float4 v0 = __ldg(&x4[i0 * 16 + c]);
        float4 v1 = __ldg(&x4[i1 * 16 + c]);
        float4 v2 = __ldg(&x4[i2 * 16 + c]);
        float4 v3 = __ldg(&x4[i3 * 16 + c]);
        a0.x += v0.x + v2.x; a0.y += v0.y + v2.y;
        a0.z += v0.z + v2.z; a0.w += v0.w + v2.w;
        a1.x += v1.x + v3.x; a1.y += v1.y + v3.y;
        a1.z += v1.z + v3.z; a1.w += v1.w + v3.w;
    }
    for (; j < end; j++) {
        int s = __ldg(&g_esrc[j]);
        float4 v = __ldg(&x4[s * 16 + c]);
        a0.x += v.x; a0.y += v.y; a0.z += v.z; a0.w += v.w;
    }
    float inv = 1.0f / fmaxf((float)d, 1.0f);
    float4 acc;
    acc.x = (a0.x + a1.x) * inv; acc.y = (a0.y + a1.y) * inv;
    acc.z = (a0.z + a1.z) * inv; acc.w = (a0.w + a1.w) * inv;
    sAgg[slot * 16 + c] = acc;
    __syncthreads();

    // --- Phase B: dense ---
    int j4 = c;
    float4 accl = make_float4(0.f, 0.f, 0.f, 0.f);
    float4 accr = make_float4(0.f, 0.f, 0.f, 0.f);
#pragma unroll 4
    for (int k4 = 0; k4 < 16; k4++) {
        float4 a  = sAgg[slot * 16 + k4];
        float4 xv = __ldg(&x4[n * 16 + k4]);
        float4 wl0 = sWl[(k4 * 4 + 0) * 16 + j4];
        float4 wl1 = sWl[(k4 * 4 + 1) * 16 + j4];
        float4 wl2 = sWl[(k4 * 4 + 2) * 16 + j4];
        float4 wl3 = sWl[(k4 * 4 + 3) * 16 + j4];
        float4 wr0 = sWr[(k4 * 4 + 0) * 16 + j4];
        float4 wr1 = sWr[(k4 * 4 + 1) * 16 + j4];
        float4 wr2 = sWr[(k4 * 4 + 2) * 16 + j4];
        float4 wr3 = sWr[(k4 * 4 + 3) * 16 + j4];
        accl.x += a.x * wl0.x + a.y * wl1.x + a.z * wl2.x + a.w * wl3.x;
        accl.y += a.x * wl0.y + a.y * wl1.y + a.z * wl2.y + a.w * wl3.y;
        accl.z += a.x * wl0.z + a.y * wl1.z + a.z * wl2.z + a.w * wl3.z;
        accl.w += a.x * wl0.w + a.y * wl1.w + a.z * wl2.w + a.w * wl3.w;
        accr.x += xv.x * wr0.x + xv.y * wr1.x + xv.z * wr2.x + xv.w * wr3.x;
        accr.y += xv.x * wr0.y + xv.y * wr1.y + xv.z * wr2.y + xv.w * wr3.y;
        accr.z += xv.x * wr0.z + xv.y * wr1.z + xv.z * wr2.z + xv.w * wr3.z;
        accr.w += xv.x * wr0.w + xv.y * wr1.w + xv.z * wr2.w + xv.w * wr3.w;
    }
    float4 bb = __ldg(&b1[j4]);
    float4 r;
    r.x = fmaxf(accl.x + accr.x + bb.x, 0.f);
    r.y = fmaxf(accl.y + accr.y + bb.y, 0.f);
    r.z = fmaxf(accl.z + accr.z + bb.z, 0.f);
    r.w = fmaxf(accl.w + accr.w + bb.w, 0.f);
    g_h[n * 16 + j4] = r;

    // --- Phase C: fused hl = h @ W2_l ---
    __syncwarp();                       // all lanes done reading sAgg (agg)
    sAgg[slot * 16 + j4] = r;           // row now holds h for this node
    __syncwarp();                       // h visible within the half-warp

    int jo = c & 7;                     // output float4 col 0..7
    int kh = (c >> 3) * 8;              // k4 half: 0 or 8
    float4 p = make_float4(0.f, 0.f, 0.f, 0.f);
#pragma unroll
    for (int kk = 0; kk < 8; kk++) {
        float4 h  = sAgg[slot * 16 + kh + kk];
        int kr = (kh + kk) * 4;
        float4 w0 = sW2l[(kr + 0) * 8 + jo];
        float4 w1 = sW2l[(kr + 1) * 8 + jo];
        float4 w2 = sW2l[(kr + 2) * 8 + jo];
        float4 w3 = sW2l[(kr + 3) * 8 + jo];
        p.x += h.x * w0.x + h.y * w1.x + h.z * w2.x + h.w * w3.x;
        p.y += h.x * w0.y + h.y * w1.y + h.z * w2.y + h.w * w3.y;
        p.z += h.x * w0.z + h.y * w1.z + h.z * w2.z + h.w * w3.z;
        p.w += h.x * w0.w + h.y * w1.w + h.z * w2.w + h.w * w3.w;
    }
    // combine the two k-halves: lane c (+) lane c+8 within each 16-group
    p.x += __shfl_down_sync(0xffffffffu, p.x, 8, 16);
    p.y += __shfl_down_sync(0xffffffffu, p.y, 8, 16);
    p.z += __shfl_down_sync(0xffffffffu, p.z, 8, 16);
    p.w += __shfl_down_sync(0xffffffffu, p.w, 8, 16);
    if (c < 8) g_hl[n * 8 + jo] = p;
}

// ---------------------------------------------------------------------------
// K6: fused layer 2: out = mean-agg(hl) + h @ W2_r + b2
// Phase A: 64 nodes x 8 chunks, 4x-unrolled gather of hl.
// ---------------------------------------------------------------------------
__global__ void __launch_bounds__(512) k_layer2(const float4* __restrict__ W2r,
                                                const float4* __restrict__ b2,
                                                float4* __restrict__ out4) {
    __shared__ float4 sW[512];
    __shared__ float4 sAgg[64 * 8];
    int tid = threadIdx.x;
    sW[tid] = W2r[tid];

    int slot = tid >> 3;          // 0..63
    int c    = tid & 7;
    int n    = blockIdx.x * 64 + slot;

    float4 a0 = make_float4(0.f, 0.f, 0.f, 0.f);
    float4 a1 = make_float4(0.f, 0.f, 0.f, 0.f);
    if (n < NN) {
        int end = g_cur[n];
        int d   = g_deg[n];
        int j   = end - d;
        for (; j + 4 <= end; j += 4) {
            int i0 = __ldg(&g_esrc[j + 0]);
            int i1 = __ldg(&g_esrc[j + 1]);
            int i2 = __ldg(&g_esrc[j + 2]);
            int i3 = __ldg(&g_esrc[j + 3]);
            float4 v0 = __ldg(&g_hl[i0 * 8 + c]);
            float4 v1 = __ldg(&g_hl[i1 * 8 + c]);
            float4 v2 = __ldg(&g_hl[i2 * 8 + c]);
            float4 v3 = __ldg(&g_hl[i3 * 8 + c]);
            a0.x += v0.x + v2.x; a0.y += v0.y + v2.y;
            a0.z += v0.z + v2.z; a0.w += v0.w + v2.w;
            a1.x += v1.x + v3.x; a1.y += v1.y + v3.y;
            a1.z += v1.z + v3.z; a1.w += v1.w + v3.w;
        }
        for (; j < end; j++) {
            int s = __ldg(&g_esrc[j]);
            float4 v = __ldg(&g_hl[s * 8 + c]);
            a0.x += v.x; a0.y += v.y; a0.z += v.z; a0.w += v.w;
        }
        float inv = 1.0f / fmaxf((float)d, 1.0f);
        a0.x = (a0.x + a1.x) * inv; a0.y = (a0.y + a1.y) * inv;
        a0.z = (a0.z + a1.z) * inv; a0.w = (a0.w + a1.w) * inv;
    }
    sAgg[slot * 8 + c] = a0;
    __syncthreads();

    int j4 = c;
    if (n >= NN) return;
    float4 a2 = make_float4(0.f, 0.f, 0.f, 0.f);
#pragma unroll 4
    for (int k4 = 0; k4 < 16; k4++) {
        float4 h  = g_h[n * 16 + k4];
        float4 w0 = sW[(k4 * 4 + 0) * 8 + j4];
        float4 w1 = sW[(k4 * 4 + 1) * 8 + j4];
        float4 w2 = sW[(k4 * 4 + 2) * 8 + j4];
        float4 w3 = sW[(k4 * 4 + 3) * 8 + j4];
        a2.x += h.x * w0.x + h.y * w1.x + h.z * w2.x + h.w * w3.x;
        a2.y += h.x * w0.y + h.y * w1.y + h.z * w2.y + h.w * w3.y;
        a2.z += h.x * w0.z + h.y * w1.z + h.z * w2.z + h.w * w3.z;
        a2.w += h.x * w0.w + h.y * w1.w + h.z * w2.w + h.w * w3.w;
    }
    float4 ag = sAgg[slot * 8 + j4];
    float4 bb = __ldg(&b2[j4]);
    float4 r;
    r.x = a2.x + ag.x + bb.x;
    r.y = a2.y + ag.y + bb.y;
    r.z = a2.z + ag.z + bb.z;
    r.w = a2.w + ag.w + bb.w;
    out4[n * 8 + j4] = r;
}

// ---------------------------------------------------------------------------
// Launch. Inputs identified BY SIZE (robust to metadata ordering):
//   x: 6,400,000   edge_index: 2,400,000   W1_l/W1_r: 4,096 (l first)
//   b1: 64         W2_l/W2_r: 2,048 (l first)   b2: 32
// output: [100000,32] f32
// ---------------------------------------------------------------------------
extern "C" void kernel_launch(void* const* d_in, const int* in_sizes, int n_in,
                              void* d_out, int out_size) {
    const float4* x4  = 0;
    const int*    ei  = 0;
    const float4* W1l = 0, *W1r = 0, *b1 = 0;
    const float4* W2l = 0, *W2r = 0, *b2 = 0;

    for (int i = 0; i < n_in; i++) {
        switch (in_sizes[i]) {
            case 6400000: x4 = (const float4*)d_in[i]; break;
            case 2400000: ei = (const int*)d_in[i]; break;
            case 4096:    if (!W1l) W1l = (const float4*)d_in[i];
                          else      W1r = (const float4*)d_in[i]; break;
            case 64:      b1 = (const float4*)d_in[i]; break;
            case 2048:    if (!W2l) W2l = (const float4*)d_in[i];
                          else      W2r = (const float4*)d_in[i]; break;
            case 32:      b2 = (const float4*)d_in[i]; break;
            default: break;
        }
    }
    if (!x4 || !ei || !W1l || !W1r || !b1 || !W2l || !W2r || !b2) return;

    float4* out4 = (float4*)d_out;

    k_zero<<<(NN + 255) / 256, 256>>>(ei);
    k_deg<<<(NE + 255) / 256, 256>>>(ei);
    k_scan1<<<NB1, 256>>>();
    k_scan2<<<1, 128>>>();
    k_scan3<<<(NN + 255) / 256, 256>>>();
    k_fill<<<(NE + 255) / 256, 256>>>(ei);
    k_layer1<<<NN / 32, 512>>>(x4, W1l, W1r, W2l, b1);
    k_layer2<<<(NN + 63) / 64, 512>>>(W2r, b2, out4);
}